// round 17
// baseline (speedup 1.0000x reference)
#include <cuda_runtime.h>
#include <cstdint>
#include <math.h>

#define N_NODES   100000
#define N_EDGES   200000
#define NNZ       2000000
#define DIM       64
#define HID       32
#define K_KEEP    1000000
#define NB_TIE    592      // 4 x 148 SMs, co-resident (launch_bounds 256,4)

// ---------------- device scratch (no allocations allowed) ----------------
struct Ctrl {
    unsigned p1, p2, Tbits;
    int rank;
    int skip;
    int ib;
    int cutoff;
};

__device__ __align__(16) float g_xa[N_NODES * HID];   // x @ W1[:64] + b1
__device__ __align__(16) float g_xb[N_NODES * HID];   // x @ W1[64:]
__device__ __align__(16) float g_eb[N_EDGES * HID];   // segment sums of xb
__device__ int      g_cnt[N_EDGES];
__device__ float    g_sum_p[N_EDGES];
__device__ float    g_sum_s[N_EDGES];
__device__ unsigned g_hist[5][2048];
__device__ Ctrl     g_ctrl;
// barrier for k_tie rare path (count returns to 0; gen increments across uses)
__device__ unsigned g_bar_count = 0;
__device__ unsigned g_bar_gen   = 0;

__device__ __forceinline__ void tie_sync() {
    __syncthreads();
    if (threadIdx.x == 0) {
        volatile unsigned* vgen = &g_bar_gen;
        unsigned gen = *vgen;
        __threadfence();
        unsigned arrived = atomicAdd(&g_bar_count, 1u);
        if (arrived == NB_TIE - 1) {
            g_bar_count = 0;
            __threadfence();
            *vgen = gen + 1;
        } else {
            while (*vgen == gen) { }
            __threadfence();
        }
    }
    __syncthreads();
}

// ---------------- zero scratch (vectorized) ----------------
__global__ void k_zero() {
    int tid = blockIdx.x * blockDim.x + threadIdx.x;
    int nt  = gridDim.x * blockDim.x;
    float4 z4 = make_float4(0.f, 0.f, 0.f, 0.f);
    float4* eb4 = reinterpret_cast<float4*>(g_eb);
    for (int i = tid; i < N_EDGES * HID / 4; i += nt) eb4[i] = z4;
    for (int i = tid; i < N_EDGES; i += nt) {
        g_cnt[i] = 0; g_sum_p[i] = 0.0f; g_sum_s[i] = 0.0f;
    }
    for (int i = tid; i < 5 * 2048; i += nt) ((unsigned*)g_hist)[i] = 0u;
    if (tid == 0) {
        g_ctrl.p1 = 0; g_ctrl.p2 = 0; g_ctrl.Tbits = 0;
        g_ctrl.rank = 0; g_ctrl.skip = 0; g_ctrl.ib = 0; g_ctrl.cutoff = 0;
    }
}

// ---------------- per-node projections: xa = x@W1a + b1, xb = x@W1b ----------------
__global__ void k_proj(const float* __restrict__ x,
                       const float* __restrict__ W1,
                       const float* __restrict__ b1) {
    __shared__ float sW[128 * 32];
    for (int i = threadIdx.x; i < 128 * 32; i += blockDim.x) sW[i] = W1[i];
    __syncthreads();
    int lane = threadIdx.x & 31;
    int warp = threadIdx.x >> 5;
    int wpb  = blockDim.x >> 5;
    float bb = b1[lane];
    for (int row = blockIdx.x * wpb + warp; row < N_NODES; row += gridDim.x * wpb) {
        float x0 = x[row * 64 + lane];
        float x1 = x[row * 64 + 32 + lane];
        float aa = bb, ab = 0.0f;
#pragma unroll
        for (int k = 0; k < 32; k++) {
            float xv = __shfl_sync(0xffffffffu, x0, k);
            aa += xv * sW[k * 32 + lane];
            ab += xv * sW[(64 + k) * 32 + lane];
        }
#pragma unroll
        for (int k = 0; k < 32; k++) {
            float xv = __shfl_sync(0xffffffffu, x1, k);
            aa += xv * sW[(32 + k) * 32 + lane];
            ab += xv * sW[(96 + k) * 32 + lane];
        }
        g_xa[row * 32 + lane] = aa;
        g_xb[row * 32 + lane] = ab;
    }
}

// ---------------- scatter: 4 nnz / thread, 8 lanes / nnz, int4 index loads, MLP=4 ----------------
__global__ void k_scatter(const int* __restrict__ V, const int* __restrict__ E) {
    int tid = blockIdx.x * blockDim.x + threadIdx.x;
    int g0  = (tid >> 3) * 4;
    int sub = tid & 7;
    if (g0 >= NNZ) return;
    int4 v4 = *reinterpret_cast<const int4*>(&V[g0]);
    int4 e4 = *reinterpret_cast<const int4*>(&E[g0]);
    float4 a = *reinterpret_cast<const float4*>(&g_xb[v4.x * 32 + sub * 4]);
    float4 b = *reinterpret_cast<const float4*>(&g_xb[v4.y * 32 + sub * 4]);
    float4 c = *reinterpret_cast<const float4*>(&g_xb[v4.z * 32 + sub * 4]);
    float4 d = *reinterpret_cast<const float4*>(&g_xb[v4.w * 32 + sub * 4]);
    asm volatile("red.global.add.v4.f32 [%0], {%1,%2,%3,%4};"
                 :: "l"(&g_eb[e4.x * 32 + sub * 4]), "f"(a.x), "f"(a.y), "f"(a.z), "f"(a.w) : "memory");
    asm volatile("red.global.add.v4.f32 [%0], {%1,%2,%3,%4};"
                 :: "l"(&g_eb[e4.y * 32 + sub * 4]), "f"(b.x), "f"(b.y), "f"(b.z), "f"(b.w) : "memory");
    asm volatile("red.global.add.v4.f32 [%0], {%1,%2,%3,%4};"
                 :: "l"(&g_eb[e4.z * 32 + sub * 4]), "f"(c.x), "f"(c.y), "f"(c.z), "f"(c.w) : "memory");
    asm volatile("red.global.add.v4.f32 [%0], {%1,%2,%3,%4};"
                 :: "l"(&g_eb[e4.w * 32 + sub * 4]), "f"(d.x), "f"(d.y), "f"(d.z), "f"(d.w) : "memory");
    if (sub == 0) {
        atomicAdd(&g_cnt[e4.x], 1);
        atomicAdd(&g_cnt[e4.y], 1);
        atomicAdd(&g_cnt[e4.z], 1);
        atomicAdd(&g_cnt[e4.w], 1);
    }
}

// ---------------- fused MLP: probs + edge prob sums (4 lanes / nnz) ----------------
__global__ void k_logits(const int* __restrict__ V, const int* __restrict__ E,
                         const float* __restrict__ W2, const float* __restrict__ b2,
                         float* __restrict__ out_probs) {
    int tid = blockIdx.x * blockDim.x + threadIdx.x;
    int g   = tid >> 2;
    int sub = tid & 3;
    if (g >= NNZ) return;
    int v = V[g], e = E[g];
    int c = g_cnt[e];
    float ic = 1.0f / (float)(c > 1 ? c : 1);
    const float4* pa = reinterpret_cast<const float4*>(&g_xa[v * 32]) + sub * 2;
    const float4* pm = reinterpret_cast<const float4*>(&g_eb[e * 32]) + sub * 2;
    const float4* pw = reinterpret_cast<const float4*>(W2) + sub * 2;
    float4 a0 = pa[0], a1 = pa[1];
    float4 m0 = pm[0], m1 = pm[1];
    float4 w0 = pw[0], w1 = pw[1];
    float part =
        fmaxf(a0.x + m0.x * ic, 0.0f) * w0.x +
        fmaxf(a0.y + m0.y * ic, 0.0f) * w0.y +
        fmaxf(a0.z + m0.z * ic, 0.0f) * w0.z +
        fmaxf(a0.w + m0.w * ic, 0.0f) * w0.w +
        fmaxf(a1.x + m1.x * ic, 0.0f) * w1.x +
        fmaxf(a1.y + m1.y * ic, 0.0f) * w1.y +
        fmaxf(a1.z + m1.z * ic, 0.0f) * w1.z +
        fmaxf(a1.w + m1.w * ic, 0.0f) * w1.w;
    part += __shfl_xor_sync(0xffffffffu, part, 2);
    part += __shfl_xor_sync(0xffffffffu, part, 1);
    if (sub == 0) {
        float z = part + b2[0];
        float p = 1.0f / (1.0f + __expf(-z));
        out_probs[g] = p;
        asm volatile("red.global.add.f32 [%0], %1;" :: "l"(&g_sum_p[e]), "f"(p) : "memory");
    }
}

// ---------------- selection: histograms phases 0..2 (vectorized) ----------------
__global__ void k_hist(const float* __restrict__ probs, int phase) {
    __shared__ unsigned sh[2048];
    for (int i = threadIdx.x; i < 2048; i += blockDim.x) sh[i] = 0u;
    __syncthreads();
    unsigned p1 = g_ctrl.p1, p2 = g_ctrl.p2;
    int tid = blockIdx.x * blockDim.x + threadIdx.x;
    int nt  = gridDim.x * blockDim.x;
    for (int t = tid; t < NNZ / 4; t += nt) {
        float4 p4 = reinterpret_cast<const float4*>(probs)[t];
        float pv[4] = {p4.x, p4.y, p4.z, p4.w};
#pragma unroll
        for (int j = 0; j < 4; j++) {
            unsigned bits = __float_as_uint(pv[j]);
            int b = -1;
            if (phase == 0)      b = (int)(bits >> 21);
            else if (phase == 1) { if ((bits >> 21) == p1) b = (int)((bits >> 10) & 2047u); }
            else                 { if ((bits >> 10) == p2) b = (int)(bits & 1023u); }
            if (b >= 0) atomicAdd(&sh[b], 1u);
        }
    }
    __syncthreads();
    for (int i = threadIdx.x; i < 2048; i += blockDim.x) {
        unsigned vv = sh[i];
        if (vv) atomicAdd(&g_hist[phase][i], vv);
    }
}

// ---------------- selection: scan + pick bucket, phases 0..2 ----------------
__global__ void k_scan(int phase) {
    __shared__ unsigned sA[2048], sB[2048];
    int n   = (phase == 2) ? 1024 : 2048;
    int tid = threadIdx.x;  // blockDim = 1024
    const unsigned* hist = g_hist[phase];
    for (int i = tid; i < n; i += 1024) sA[i] = hist[i];
    __syncthreads();
    unsigned *in = sA, *out = sB;
    for (int off = 1; off < n; off <<= 1) {
        for (int i = tid; i < n; i += 1024) {
            unsigned add = (i + off < n) ? in[i + off] : 0u;   // descending (suffix)
            out[i] = in[i] + add;
        }
        __syncthreads();
        unsigned* t = in; in = out; out = t;
    }
    int rank = (phase == 0) ? K_KEEP : g_ctrl.rank;
    for (int i = tid; i < n; i += 1024) {
        unsigned nxt = (i + 1 < n) ? in[i + 1] : 0u;
        if ((int)in[i] >= rank && (int)nxt < rank) {
            if (phase == 0)      { g_ctrl.p1 = (unsigned)i; g_ctrl.rank = rank - (int)nxt; }
            else if (phase == 1) { g_ctrl.p2 = (g_ctrl.p1 << 11) | (unsigned)i; g_ctrl.rank = rank - (int)nxt; }
            else {
                g_ctrl.Tbits = (g_ctrl.p2 << 10) | (unsigned)i;
                int r   = rank - (int)nxt;
                int neq = (int)(in[i] - nxt);
                if (r >= neq) { g_ctrl.skip = 1; g_ctrl.cutoff = 0x7fffffff; }
                else          { g_ctrl.skip = 0; g_ctrl.rank = r; }
            }
        }
    }
}

// ---------------- k_tie: phases 3+4 in one kernel (rare path) ----------------
__device__ void tie_scan(int phase, unsigned* sA, unsigned* sB) {
    int n = (phase == 3) ? 1024 : 2048;
    const unsigned* hist = g_hist[phase];
    int nt = blockDim.x;
    for (int i = threadIdx.x; i < n; i += nt) sA[i] = hist[i];
    __syncthreads();
    unsigned *in = sA, *out = sB;
    for (int off = 1; off < n; off <<= 1) {
        for (int i = threadIdx.x; i < n; i += nt) {
            unsigned add = (i >= off) ? in[i - off] : 0u;   // ascending (prefix)
            out[i] = in[i] + add;
        }
        __syncthreads();
        unsigned* t = in; in = out; out = t;
    }
    int rank = g_ctrl.rank;
    for (int i = threadIdx.x; i < n; i += nt) {
        unsigned prv = (i > 0) ? in[i - 1] : 0u;
        if ((int)in[i] >= rank && (int)prv < rank) {
            if (phase == 3) { g_ctrl.ib = i; g_ctrl.rank = rank - (int)prv; }
            else            { g_ctrl.cutoff = (g_ctrl.ib << 11) | i; }
        }
    }
    __syncthreads();
}

__global__ void __launch_bounds__(256, 4)
k_tie(const float* __restrict__ probs) {
    __shared__ unsigned sA[2048], sB[2048];
    if (g_ctrl.skip) return;                       // common case: ~launch cost only
    unsigned Tb = g_ctrl.Tbits;
    int tid = blockIdx.x * blockDim.x + threadIdx.x;
    int nt  = gridDim.x * blockDim.x;

    // hist3: index-high buckets among exact ties
    for (int i = threadIdx.x; i < 1024; i += blockDim.x) sA[i] = 0u;
    __syncthreads();
    for (int t = tid; t < NNZ / 4; t += nt) {
        float4 p4 = reinterpret_cast<const float4*>(probs)[t];
        float pv[4] = {p4.x, p4.y, p4.z, p4.w};
#pragma unroll
        for (int j = 0; j < 4; j++) {
            if (__float_as_uint(pv[j]) == Tb)
                atomicAdd(&sA[(unsigned)(4 * t + j) >> 11], 1u);
        }
    }
    __syncthreads();
    for (int i = threadIdx.x; i < 1024; i += blockDim.x) {
        unsigned v = sA[i];
        if (v) atomicAdd(&g_hist[3][i], v);
    }
    tie_sync();

    if (blockIdx.x == 0) tie_scan(3, sA, sB);      // -> g_ctrl.ib, rank
    tie_sync();

    int ib = g_ctrl.ib;
    // hist4: index-low buckets within ib
    for (int i = threadIdx.x; i < 2048; i += blockDim.x) sA[i] = 0u;
    __syncthreads();
    for (int t = tid; t < NNZ / 4; t += nt) {
        float4 p4 = reinterpret_cast<const float4*>(probs)[t];
        float pv[4] = {p4.x, p4.y, p4.z, p4.w};
#pragma unroll
        for (int j = 0; j < 4; j++) {
            int idx = 4 * t + j;
            if (__float_as_uint(pv[j]) == Tb && (idx >> 11) == ib)
                atomicAdd(&sA[idx & 2047], 1u);
        }
    }
    __syncthreads();
    for (int i = threadIdx.x; i < 2048; i += blockDim.x) {
        unsigned v = sA[i];
        if (v) atomicAdd(&g_hist[4][i], v);
    }
    tie_sync();

    if (blockIdx.x == 0) tie_scan(4, sA, sB);      // -> g_ctrl.cutoff
}

// ---------------- hard/soft mask + edge soft sums (vectorized, guarded red) ----------------
__global__ void k_mask(const int* __restrict__ E, const float* __restrict__ probs,
                       float* __restrict__ soft, float* __restrict__ hard) {
    int t = blockIdx.x * blockDim.x + threadIdx.x;
    if (t >= NNZ / 4) return;
    float4 p4 = reinterpret_cast<const float4*>(probs)[t];
    int4   e4 = reinterpret_cast<const int4*>(E)[t];
    unsigned T = g_ctrl.Tbits;
    int cut = g_ctrl.cutoff;
    int base = t * 4;
    float pv[4] = {p4.x, p4.y, p4.z, p4.w};
    int   ev[4] = {e4.x, e4.y, e4.z, e4.w};
    float sf[4], hf[4];
#pragma unroll
    for (int j = 0; j < 4; j++) {
        unsigned bits = __float_as_uint(pv[j]);
        bool h = (bits > T) || (bits == T && (base + j) <= cut);
        hf[j] = h ? 1.0f : 0.0f;
        sf[j] = h ? ((1.0f - pv[j]) + pv[j]) : 0.0f;
        if (h)
            asm volatile("red.global.add.f32 [%0], %1;"
                         :: "l"(&g_sum_s[ev[j]]), "f"(sf[j]) : "memory");
    }
    reinterpret_cast<float4*>(soft)[t] = make_float4(sf[0], sf[1], sf[2], sf[3]);
    reinterpret_cast<float4*>(hard)[t] = make_float4(hf[0], hf[1], hf[2], hf[3]);
}

// ---------------- edge outputs (vectorized) ----------------
__global__ void k_edges(float* __restrict__ ep, float* __restrict__ es, float* __restrict__ eh) {
    int t = blockIdx.x * blockDim.x + threadIdx.x;
    if (t >= N_EDGES / 4) return;
    int4   c4 = reinterpret_cast<const int4*>(g_cnt)[t];
    float4 sp = reinterpret_cast<const float4*>(g_sum_p)[t];
    float4 ss = reinterpret_cast<const float4*>(g_sum_s)[t];
    float c0 = (float)(c4.x > 1 ? c4.x : 1);
    float c1 = (float)(c4.y > 1 ? c4.y : 1);
    float c2 = (float)(c4.z > 1 ? c4.z : 1);
    float c3 = (float)(c4.w > 1 ? c4.w : 1);
    reinterpret_cast<float4*>(ep)[t] = make_float4(sp.x / c0, sp.y / c1, sp.z / c2, sp.w / c3);
    reinterpret_cast<float4*>(es)[t] = make_float4(ss.x / c0, ss.y / c1, ss.z / c2, ss.w / c3);
    reinterpret_cast<float4*>(eh)[t] = make_float4(ss.x > 0.f ? 1.f : 0.f, ss.y > 0.f ? 1.f : 0.f,
                                                   ss.z > 0.f ? 1.f : 0.f, ss.w > 0.f ? 1.f : 0.f);
}

// ---------------- launcher ----------------
extern "C" void kernel_launch(void* const* d_in, const int* in_sizes, int n_in,
                              void* d_out, int out_size) {
    const float* x  = (const float*)d_in[0];
    const int*   V  = (const int*)d_in[1];
    const int*   E  = (const int*)d_in[2];
    const float* W1 = (const float*)d_in[3];
    const float* b1 = (const float*)d_in[4];
    const float* W2 = (const float*)d_in[5];
    const float* b2 = (const float*)d_in[6];

    float* out   = (float*)d_out;
    float* probs = out;
    float* soft  = out + NNZ;
    float* hard  = out + 2 * NNZ;
    float* ep    = out + 3 * NNZ;
    float* es    = ep + N_EDGES;
    float* eh    = es + N_EDGES;

    k_zero<<<512, 256>>>();                                          // 1
    k_proj<<<512, 256>>>(x, W1, b1);                                 // 2
    k_scatter<<<(NNZ * 2 + 255) / 256, 256>>>(V, E);                 // 3
    k_logits<<<(NNZ * 4 + 255) / 256, 256>>>(V, E, W2, b2, probs);   // 4 <- profiled
    for (int ph = 0; ph < 3; ph++) {
        k_hist<<<512, 256>>>(probs, ph);
        k_scan<<<1, 1024>>>(ph);
    }
    k_tie<<<NB_TIE, 256>>>(probs);                                   // phases 3+4 (fast exit)
    k_mask<<<(NNZ / 4 + 255) / 256, 256>>>(E, probs, soft, hard);
    k_edges<<<(N_EDGES / 4 + 255) / 256, 256>>>(ep, es, eh);
}